// round 3
// baseline (speedup 1.0000x reference)
#include <cuda_runtime.h>

#define N_NODES 50000
#define N_EDGES 800000
#define N_GRAPHS 256
#define DD 128
#define DV (DD / 4)            // float4 vectors per node row = 32
#define NLAYERS 3
#define TILE 16
#define BN_EPS 1e-5f

// -------- scratch (no allocations allowed); float4 => 16B-aligned --------
__device__ float4 g_x[N_NODES * DV];     // current node features
__device__ float4 g_agg[N_NODES * DV];   // neighbor sums
__device__ float  g_stats[2 * DD];       // per-feature sum, sumsq
__device__ float4 g_pool[N_GRAPHS * DV]; // per-graph sums
__device__ float  g_cnt[N_GRAPHS];       // per-graph counts

// -------- edge scatter: agg[dst] += x[src], one warp per edge --------
__global__ void k_scatter(const int* __restrict__ ei) {
    int gtid = blockIdx.x * blockDim.x + threadIdx.x;
    int e = gtid >> 5;
    int lane = gtid & 31;
    if (e >= N_EDGES) return;
    unsigned s = (unsigned)ei[e];
    unsigned d = (unsigned)ei[N_EDGES + e];
    if (s >= N_NODES || d >= N_NODES) return;  // guard: bad index -> skip (diagnosable)
    float4 v = g_x[s * DV + lane];
    atomicAdd(&g_agg[d * DV + lane], v);
}

// -------- fused MLP: h=(1+eps)x+agg; t=relu(h@W1+b1); y=relu(t@W2+b2);
//          y -> g_x (in place); accumulate BN stats --------
extern __shared__ float smem[];
__global__ void __launch_bounds__(256, 1) k_mlp(
    const float* __restrict__ W1, const float* __restrict__ b1,
    const float* __restrict__ W2, const float* __restrict__ b2,
    const float* __restrict__ epsp)
{
    float* sW1 = smem;                    // 128*128
    float* sW2 = sW1 + DD * DD;           // 128*128
    float* sb1 = sW2 + DD * DD;           // 128
    float* sb2 = sb1 + DD;                // 128
    float* sh  = sb2 + DD;                // TILE*128
    float* st  = sh + TILE * DD;          // TILE*128
    float* sst = st + TILE * DD;          // 2*128

    const int t = threadIdx.x;

    // stage weights + biases
    for (int i = t; i < DD * DD / 4; i += blockDim.x) {
        reinterpret_cast<float4*>(sW1)[i] = reinterpret_cast<const float4*>(W1)[i];
        reinterpret_cast<float4*>(sW2)[i] = reinterpret_cast<const float4*>(W2)[i];
    }
    if (t < DD) { sb1[t] = b1[t]; sb2[t] = b2[t]; }
    const float eps1 = 1.0f + epsp[0];

    const int og = (t & 31) * 4;   // 4 output features
    const int ig = t >> 5;         // node group: nodes 2*ig, 2*ig+1
    const int i0 = ig * 2, i1 = ig * 2 + 1;

    float s0 = 0.f, s1 = 0.f, s2 = 0.f, s3 = 0.f;
    float q0 = 0.f, q1 = 0.f, q2 = 0.f, q3 = 0.f;

    __syncthreads();

    for (int tile = blockIdx.x; tile < N_NODES / TILE; tile += gridDim.x) {
        const int nb = tile * TILE;
        // h-tile: (1+eps)*x + agg
        for (int i = t; i < TILE * DV; i += blockDim.x) {
            float4 xv = g_x[nb * DV + i];
            float4 av = g_agg[nb * DV + i];
            float4 hv;
            hv.x = fmaf(eps1, xv.x, av.x);
            hv.y = fmaf(eps1, xv.y, av.y);
            hv.z = fmaf(eps1, xv.z, av.z);
            hv.w = fmaf(eps1, xv.w, av.w);
            reinterpret_cast<float4*>(sh)[i] = hv;
        }
        __syncthreads();

        // GEMM1: t = relu(h @ W1 + b1)
        float a00 = sb1[og], a01 = sb1[og+1], a02 = sb1[og+2], a03 = sb1[og+3];
        float a10 = a00, a11 = a01, a12 = a02, a13 = a03;
        #pragma unroll 4
        for (int d = 0; d < DD; d++) {
            float h0 = sh[i0 * DD + d];
            float h1 = sh[i1 * DD + d];
            float4 w = *reinterpret_cast<const float4*>(&sW1[d * DD + og]);
            a00 = fmaf(h0, w.x, a00); a01 = fmaf(h0, w.y, a01);
            a02 = fmaf(h0, w.z, a02); a03 = fmaf(h0, w.w, a03);
            a10 = fmaf(h1, w.x, a10); a11 = fmaf(h1, w.y, a11);
            a12 = fmaf(h1, w.z, a12); a13 = fmaf(h1, w.w, a13);
        }
        float4 t0 = make_float4(fmaxf(a00,0.f), fmaxf(a01,0.f), fmaxf(a02,0.f), fmaxf(a03,0.f));
        float4 t1 = make_float4(fmaxf(a10,0.f), fmaxf(a11,0.f), fmaxf(a12,0.f), fmaxf(a13,0.f));
        *reinterpret_cast<float4*>(&st[i0 * DD + og]) = t0;
        *reinterpret_cast<float4*>(&st[i1 * DD + og]) = t1;
        __syncthreads();

        // GEMM2: y = relu(t @ W2 + b2)
        float c00 = sb2[og], c01 = sb2[og+1], c02 = sb2[og+2], c03 = sb2[og+3];
        float c10 = c00, c11 = c01, c12 = c02, c13 = c03;
        #pragma unroll 4
        for (int d = 0; d < DD; d++) {
            float u0 = st[i0 * DD + d];
            float u1 = st[i1 * DD + d];
            float4 w = *reinterpret_cast<const float4*>(&sW2[d * DD + og]);
            c00 = fmaf(u0, w.x, c00); c01 = fmaf(u0, w.y, c01);
            c02 = fmaf(u0, w.z, c02); c03 = fmaf(u0, w.w, c03);
            c10 = fmaf(u1, w.x, c10); c11 = fmaf(u1, w.y, c11);
            c12 = fmaf(u1, w.z, c12); c13 = fmaf(u1, w.w, c13);
        }
        float y00 = fmaxf(c00,0.f), y01 = fmaxf(c01,0.f), y02 = fmaxf(c02,0.f), y03 = fmaxf(c03,0.f);
        float y10 = fmaxf(c10,0.f), y11 = fmaxf(c11,0.f), y12 = fmaxf(c12,0.f), y13 = fmaxf(c13,0.f);

        g_x[(nb + i0) * DV + (og >> 2)] = make_float4(y00,y01,y02,y03);
        g_x[(nb + i1) * DV + (og >> 2)] = make_float4(y10,y11,y12,y13);

        s0 += y00 + y10; s1 += y01 + y11; s2 += y02 + y12; s3 += y03 + y13;
        q0 += y00*y00 + y10*y10; q1 += y01*y01 + y11*y11;
        q2 += y02*y02 + y12*y12; q3 += y03*y03 + y13*y13;
        __syncthreads();
    }

    // block-level stat reduction -> global
    if (t < 2 * DD) sst[t] = 0.f;
    __syncthreads();
    atomicAdd(&sst[og],        s0); atomicAdd(&sst[og+1],      s1);
    atomicAdd(&sst[og+2],      s2); atomicAdd(&sst[og+3],      s3);
    atomicAdd(&sst[DD+og],     q0); atomicAdd(&sst[DD+og+1],   q1);
    atomicAdd(&sst[DD+og+2],   q2); atomicAdd(&sst[DD+og+3],   q3);
    __syncthreads();
    if (t < DD) {
        atomicAdd(&g_stats[t],      sst[t]);
        atomicAdd(&g_stats[DD + t], sst[DD + t]);
    }
}

// -------- batchnorm apply (in place on g_x) --------
__global__ void k_bn(const float* __restrict__ gamma, const float* __restrict__ beta) {
    int idx = blockIdx.x * blockDim.x + threadIdx.x;
    if (idx >= N_NODES * DD) return;
    int f = idx & (DD - 1);
    float s = g_stats[f];
    float q = g_stats[DD + f];
    const float invN = 1.0f / (float)N_NODES;
    float mu = s * invN;
    float var = fmaf(q, invN, -mu * mu);
    float sc = gamma[f] * rsqrtf(var + BN_EPS);
    float* gx = reinterpret_cast<float*>(g_x);
    gx[idx] = fmaf(gx[idx] - mu, sc, beta[f]);
}

// -------- global mean pool (sums + counts) --------
__global__ void k_pool(const int* __restrict__ batch) {
    int idx = blockIdx.x * blockDim.x + threadIdx.x;
    int n = idx >> 5;
    int k = idx & 31;
    if (n >= N_NODES) return;
    unsigned g = (unsigned)batch[n];
    if (g >= N_GRAPHS) return;  // guard
    float4 v = g_x[n * DV + k];
    atomicAdd(&g_pool[g * DV + k], v);
    if (k == 0) atomicAdd(&g_cnt[g], 1.0f);
}

// -------- head: out = (pool/cnt) @ We + be --------
__global__ void k_final(const float* __restrict__ We, const float* __restrict__ be,
                        float* __restrict__ out) {
    __shared__ float sp[DD];
    int b = blockIdx.x;
    int o = threadIdx.x;
    float c = fmaxf(g_cnt[b], 1.0f);
    sp[o] = reinterpret_cast<const float*>(g_pool)[b * DD + o] / c;
    __syncthreads();
    float acc = be[o];
    #pragma unroll 4
    for (int d = 0; d < DD; d++) acc = fmaf(sp[d], We[d * DD + o], acc);
    out[b * DD + o] = acc;
}

extern "C" void kernel_launch(void* const* d_in, const int* in_sizes, int n_in,
                              void* d_out, int out_size) {
    const float* x     = (const float*)d_in[0];
    const int*   ei    = (const int*)d_in[1];     // edge_index: int32 (JAX x64 disabled)
    const int*   batch = (const int*)d_in[2];     // batch: int32
    const float* W1    = (const float*)d_in[3];
    const float* b1    = (const float*)d_in[4];
    const float* W2    = (const float*)d_in[5];
    const float* b2    = (const float*)d_in[6];
    const float* eps   = (const float*)d_in[7];
    const float* gamma = (const float*)d_in[8];
    const float* beta  = (const float*)d_in[9];
    const float* We    = (const float*)d_in[10];
    const float* be    = (const float*)d_in[11];
    float* out = (float*)d_out;

    void *p_x, *p_agg, *p_stats, *p_pool, *p_cnt;
    cudaGetSymbolAddress(&p_x, g_x);
    cudaGetSymbolAddress(&p_agg, g_agg);
    cudaGetSymbolAddress(&p_stats, g_stats);
    cudaGetSymbolAddress(&p_pool, g_pool);
    cudaGetSymbolAddress(&p_cnt, g_cnt);

    const int mlp_smem = (2 * DD * DD + 2 * DD + 2 * TILE * DD + 2 * DD) * (int)sizeof(float);
    cudaFuncSetAttribute(k_mlp, cudaFuncAttributeMaxDynamicSharedMemorySize, mlp_smem);

    // load features
    cudaMemcpyAsync(p_x, x, (size_t)N_NODES * DD * sizeof(float),
                    cudaMemcpyDeviceToDevice, 0);

    const int scatter_blocks = (N_EDGES * 32 + 255) / 256;
    const int bn_blocks = (N_NODES * DD + 255) / 256;

    for (int l = 0; l < NLAYERS; l++) {
        cudaMemsetAsync(p_agg, 0, (size_t)N_NODES * DD * sizeof(float), 0);
        cudaMemsetAsync(p_stats, 0, 2 * DD * sizeof(float), 0);
        k_scatter<<<scatter_blocks, 256>>>(ei);
        k_mlp<<<148, 256, mlp_smem>>>(W1 + l * DD * DD, b1 + l * DD,
                                      W2 + l * DD * DD, b2 + l * DD, eps + l);
        k_bn<<<bn_blocks, 256>>>(gamma + l * DD, beta + l * DD);
    }

    cudaMemsetAsync(p_pool, 0, (size_t)N_GRAPHS * DD * sizeof(float), 0);
    cudaMemsetAsync(p_cnt, 0, N_GRAPHS * sizeof(float), 0);
    const int pool_blocks = (N_NODES * 32 + 255) / 256;
    k_pool<<<pool_blocks, 256>>>(batch);
    k_final<<<N_GRAPHS, DD>>>(We, be, out);
}

// round 4
// speedup vs baseline: 1.2575x; 1.2575x over previous
#include <cuda_runtime.h>

#define N_NODES 50000
#define N_EDGES 800000
#define N_GRAPHS 256
#define DD 128
#define DV 32                   // float4 per node row
#define NLAYERS 3
#define TILE 32
#define NTILES ((N_NODES + TILE - 1) / TILE)
#define BN_EPS 1e-5f

// -------- scratch (16B-aligned via float4) --------
__device__ float4 g_xa[N_NODES * DV];
__device__ float4 g_xb[N_NODES * DV];
__device__ int    g_deg[N_NODES];
__device__ int    g_off[N_NODES + 1];
__device__ int    g_cur[N_NODES];
__device__ int    g_csr[N_EDGES];
__device__ float  g_stats[2 * DD];
__device__ float  g_sc[DD];
__device__ float  g_sh[DD];
__device__ float4 g_pool[N_GRAPHS * DV];
__device__ float  g_cnt[N_GRAPHS];

// -------- CSR build --------
__global__ void k_deg(const int* __restrict__ ei) {
    int e = blockIdx.x * blockDim.x + threadIdx.x;
    if (e >= N_EDGES) return;
    unsigned d = (unsigned)ei[N_EDGES + e];
    if (d < N_NODES) atomicAdd(&g_deg[d], 1);
}

__global__ void k_scan() {   // single block, 1024 threads: exclusive scan of g_deg
    __shared__ int sbuf[1024];
    __shared__ int carry;
    if (threadIdx.x == 0) carry = 0;
    __syncthreads();
    for (int base = 0; base < N_NODES; base += 1024) {
        int i = base + threadIdx.x;
        int v = (i < N_NODES) ? g_deg[i] : 0;
        sbuf[threadIdx.x] = v;
        __syncthreads();
        for (int ofs = 1; ofs < 1024; ofs <<= 1) {
            int tv = (threadIdx.x >= ofs) ? sbuf[threadIdx.x - ofs] : 0;
            __syncthreads();
            sbuf[threadIdx.x] += tv;
            __syncthreads();
        }
        if (i < N_NODES) g_off[i + 1] = carry + sbuf[threadIdx.x];
        __syncthreads();
        if (threadIdx.x == 0) carry += sbuf[1023];
        __syncthreads();
    }
    if (threadIdx.x == 0) g_off[0] = 0;
}

__global__ void k_fill(const int* __restrict__ ei) {
    int e = blockIdx.x * blockDim.x + threadIdx.x;
    if (e >= N_EDGES) return;
    unsigned s = (unsigned)ei[e];
    unsigned d = (unsigned)ei[N_EDGES + e];
    if (s >= N_NODES || d >= N_NODES) return;
    int pos = atomicAdd(&g_cur[d], 1);
    g_csr[g_off[d] + pos] = (int)s;
}

// -------- BN fold params --------
__global__ void k_bninit() {
    int t = threadIdx.x;
    g_sc[t] = 1.0f;
    g_sh[t] = 0.0f;
}
__global__ void k_bnparam(const float* __restrict__ gamma, const float* __restrict__ beta) {
    int t = threadIdx.x;
    const float invN = 1.0f / (float)N_NODES;
    float s = g_stats[t], q = g_stats[DD + t];
    float mu = s * invN;
    float var = fmaf(q, invN, -mu * mu);
    float sc = gamma[t] * rsqrtf(var + BN_EPS);
    g_sc[t] = sc;
    g_sh[t] = beta[t] - mu * sc;
}

// -------- fused layer: CSR gather + BN-fold + MLP + stats --------
extern __shared__ float smem[];
__global__ void __launch_bounds__(256, 1) k_mlp(
    const float4* __restrict__ in, float4* __restrict__ out,
    const float* __restrict__ W1, const float* __restrict__ b1,
    const float* __restrict__ W2, const float* __restrict__ b2,
    const float* __restrict__ epsp)
{
    float* sW1 = smem;                    // 128*128
    float* sW2 = sW1 + DD * DD;           // 128*128
    float* sb1 = sW2 + DD * DD;           // 128
    float* sb2 = sb1 + DD;                // 128
    float* ssc = sb2 + DD;                // 128
    float* ssh = ssc + DD;                // 128
    float* shb = ssh + DD;                // TILE*128
    float* stb = shb + TILE * DD;         // TILE*128
    float* sst = stb + TILE * DD;         // 2*128

    const int t = threadIdx.x;
    const int lane = t & 31, warp = t >> 5;

    for (int i = t; i < DD * DD / 4; i += 256) {
        reinterpret_cast<float4*>(sW1)[i] = reinterpret_cast<const float4*>(W1)[i];
        reinterpret_cast<float4*>(sW2)[i] = reinterpret_cast<const float4*>(W2)[i];
    }
    if (t < DD) { sb1[t] = b1[t]; sb2[t] = b2[t]; ssc[t] = g_sc[t]; ssh[t] = g_sh[t]; }
    const float eps1 = 1.0f + epsp[0];
    __syncthreads();

    const float4 sc4 = reinterpret_cast<const float4*>(ssc)[lane];
    const float4 sh4 = reinterpret_cast<const float4*>(ssh)[lane];
    const float b1x = sb1[lane*4], b1y = sb1[lane*4+1], b1z = sb1[lane*4+2], b1w = sb1[lane*4+3];
    const float b2x = sb2[lane*4], b2y = sb2[lane*4+1], b2z = sb2[lane*4+2], b2w = sb2[lane*4+3];

    float sv[4] = {0.f, 0.f, 0.f, 0.f};
    float qv[4] = {0.f, 0.f, 0.f, 0.f};

    for (int tile = blockIdx.x; tile < NTILES; tile += gridDim.x) {
        const int nb = tile * TILE;

        // ---- gather (CSR) + BN-fold + GIN combine -> h tile ----
        #pragma unroll
        for (int r = 0; r < 4; r++) {
            int node = nb + warp * 4 + r;
            float4 acc = make_float4(0.f, 0.f, 0.f, 0.f);
            float4 xv  = make_float4(0.f, 0.f, 0.f, 0.f);
            float fdeg = 0.f;
            if (node < N_NODES) {
                int beg = g_off[node], end = g_off[node + 1];
                fdeg = (float)(end - beg);
                int e = beg;
                for (; e + 1 < end; e += 2) {
                    int j0 = g_csr[e], j1 = g_csr[e + 1];
                    float4 v0 = in[j0 * DV + lane];
                    float4 v1 = in[j1 * DV + lane];
                    acc.x += v0.x + v1.x; acc.y += v0.y + v1.y;
                    acc.z += v0.z + v1.z; acc.w += v0.w + v1.w;
                }
                if (e < end) {
                    int j0 = g_csr[e];
                    float4 v0 = in[j0 * DV + lane];
                    acc.x += v0.x; acc.y += v0.y; acc.z += v0.z; acc.w += v0.w;
                }
                xv = in[node * DV + lane];
            }
            float f = eps1 + fdeg;
            float4 h;
            h.x = fmaf(sc4.x, fmaf(eps1, xv.x, acc.x), f * sh4.x);
            h.y = fmaf(sc4.y, fmaf(eps1, xv.y, acc.y), f * sh4.y);
            h.z = fmaf(sc4.z, fmaf(eps1, xv.z, acc.z), f * sh4.z);
            h.w = fmaf(sc4.w, fmaf(eps1, xv.w, acc.w), f * sh4.w);
            reinterpret_cast<float4*>(shb)[(warp * 4 + r) * DV + lane] = h;
        }
        __syncthreads();

        // ---- GEMM1: t = relu(h @ W1 + b1), 4 nodes x 4 outs per thread ----
        {
            float a[4][4];
            #pragma unroll
            for (int r = 0; r < 4; r++) { a[r][0]=b1x; a[r][1]=b1y; a[r][2]=b1z; a[r][3]=b1w; }
            #pragma unroll 8
            for (int d0 = 0; d0 < DD; d0 += 4) {
                float4 hv[4];
                #pragma unroll
                for (int r = 0; r < 4; r++)
                    hv[r] = reinterpret_cast<const float4*>(shb)[(warp*4 + r)*DV + (d0 >> 2)];
                #pragma unroll
                for (int dd = 0; dd < 4; dd++) {
                    float4 w = reinterpret_cast<const float4*>(sW1)[(d0 + dd)*DV + lane];
                    #pragma unroll
                    for (int r = 0; r < 4; r++) {
                        float hr = (dd == 0) ? hv[r].x : (dd == 1) ? hv[r].y : (dd == 2) ? hv[r].z : hv[r].w;
                        a[r][0] = fmaf(hr, w.x, a[r][0]);
                        a[r][1] = fmaf(hr, w.y, a[r][1]);
                        a[r][2] = fmaf(hr, w.z, a[r][2]);
                        a[r][3] = fmaf(hr, w.w, a[r][3]);
                    }
                }
            }
            #pragma unroll
            for (int r = 0; r < 4; r++) {
                float4 tv = make_float4(fmaxf(a[r][0],0.f), fmaxf(a[r][1],0.f),
                                        fmaxf(a[r][2],0.f), fmaxf(a[r][3],0.f));
                reinterpret_cast<float4*>(stb)[(warp*4 + r)*DV + lane] = tv;
            }
        }
        __syncthreads();

        // ---- GEMM2: y = relu(t @ W2 + b2); write out; BN stats ----
        {
            float c[4][4];
            #pragma unroll
            for (int r = 0; r < 4; r++) { c[r][0]=b2x; c[r][1]=b2y; c[r][2]=b2z; c[r][3]=b2w; }
            #pragma unroll 8
            for (int d0 = 0; d0 < DD; d0 += 4) {
                float4 uv[4];
                #pragma unroll
                for (int r = 0; r < 4; r++)
                    uv[r] = reinterpret_cast<const float4*>(stb)[(warp*4 + r)*DV + (d0 >> 2)];
                #pragma unroll
                for (int dd = 0; dd < 4; dd++) {
                    float4 w = reinterpret_cast<const float4*>(sW2)[(d0 + dd)*DV + lane];
                    #pragma unroll
                    for (int r = 0; r < 4; r++) {
                        float ur = (dd == 0) ? uv[r].x : (dd == 1) ? uv[r].y : (dd == 2) ? uv[r].z : uv[r].w;
                        c[r][0] = fmaf(ur, w.x, c[r][0]);
                        c[r][1] = fmaf(ur, w.y, c[r][1]);
                        c[r][2] = fmaf(ur, w.z, c[r][2]);
                        c[r][3] = fmaf(ur, w.w, c[r][3]);
                    }
                }
            }
            #pragma unroll
            for (int r = 0; r < 4; r++) {
                int node = nb + warp * 4 + r;
                if (node < N_NODES) {
                    float4 y = make_float4(fmaxf(c[r][0],0.f), fmaxf(c[r][1],0.f),
                                           fmaxf(c[r][2],0.f), fmaxf(c[r][3],0.f));
                    out[node * DV + lane] = y;
                    sv[0] += y.x; sv[1] += y.y; sv[2] += y.z; sv[3] += y.w;
                    qv[0] += y.x*y.x; qv[1] += y.y*y.y; qv[2] += y.z*y.z; qv[3] += y.w*y.w;
                }
            }
        }
        __syncthreads();
    }

    // ---- block stat reduction -> global ----
    if (t < 2 * DD) sst[t] = 0.f;
    __syncthreads();
    const int og = lane * 4;
    atomicAdd(&sst[og],      sv[0]); atomicAdd(&sst[og+1],    sv[1]);
    atomicAdd(&sst[og+2],    sv[2]); atomicAdd(&sst[og+3],    sv[3]);
    atomicAdd(&sst[DD+og],   qv[0]); atomicAdd(&sst[DD+og+1], qv[1]);
    atomicAdd(&sst[DD+og+2], qv[2]); atomicAdd(&sst[DD+og+3], qv[3]);
    __syncthreads();
    if (t < DD) {
        atomicAdd(&g_stats[t],      sst[t]);
        atomicAdd(&g_stats[DD + t], sst[DD + t]);
    }
}

// -------- global mean pool on raw y3 --------
__global__ void k_pool(const int* __restrict__ batch, const float4* __restrict__ in) {
    int idx = blockIdx.x * blockDim.x + threadIdx.x;
    int n = idx >> 5;
    int k = idx & 31;
    if (n >= N_NODES) return;
    unsigned g = (unsigned)batch[n];
    if (g >= N_GRAPHS) return;
    float4 v = in[n * DV + k];
    atomicAdd(&g_pool[g * DV + k], v);
    if (k == 0) atomicAdd(&g_cnt[g], 1.0f);
}

// -------- head: out = (BN-fold(pool/cnt)) @ We + be --------
__global__ void k_final(const float* __restrict__ We, const float* __restrict__ be,
                        float* __restrict__ out) {
    __shared__ float sp[DD];
    int b = blockIdx.x;
    int o = threadIdx.x;
    float c = fmaxf(g_cnt[b], 1.0f);
    float sum = reinterpret_cast<const float*>(g_pool)[b * DD + o];
    sp[o] = fmaf(g_sc[o], sum / c, g_sh[o]);
    __syncthreads();
    float acc = be[o];
    #pragma unroll 4
    for (int d = 0; d < DD; d++) acc = fmaf(sp[d], We[d * DD + o], acc);
    out[b * DD + o] = acc;
}

extern "C" void kernel_launch(void* const* d_in, const int* in_sizes, int n_in,
                              void* d_out, int out_size) {
    const float* x     = (const float*)d_in[0];
    const int*   ei    = (const int*)d_in[1];
    const int*   batch = (const int*)d_in[2];
    const float* W1    = (const float*)d_in[3];
    const float* b1    = (const float*)d_in[4];
    const float* W2    = (const float*)d_in[5];
    const float* b2    = (const float*)d_in[6];
    const float* eps   = (const float*)d_in[7];
    const float* gamma = (const float*)d_in[8];
    const float* beta  = (const float*)d_in[9];
    const float* We    = (const float*)d_in[10];
    const float* be    = (const float*)d_in[11];
    float* out = (float*)d_out;

    void *p_xa, *p_xb, *p_deg, *p_cur, *p_stats, *p_pool, *p_cnt;
    cudaGetSymbolAddress(&p_xa, g_xa);
    cudaGetSymbolAddress(&p_xb, g_xb);
    cudaGetSymbolAddress(&p_deg, g_deg);
    cudaGetSymbolAddress(&p_cur, g_cur);
    cudaGetSymbolAddress(&p_stats, g_stats);
    cudaGetSymbolAddress(&p_pool, g_pool);
    cudaGetSymbolAddress(&p_cnt, g_cnt);

    const int mlp_smem = (2*DD*DD + 4*DD + 2*TILE*DD + 2*DD) * (int)sizeof(float);
    static int attr_set = 0;
    cudaFuncSetAttribute(k_mlp, cudaFuncAttributeMaxDynamicSharedMemorySize, mlp_smem);
    (void)attr_set;

    // load features
    cudaMemcpyAsync(p_xa, x, (size_t)N_NODES * DD * sizeof(float),
                    cudaMemcpyDeviceToDevice, 0);

    // CSR build (once; reused across layers)
    cudaMemsetAsync(p_deg, 0, N_NODES * sizeof(int), 0);
    cudaMemsetAsync(p_cur, 0, N_NODES * sizeof(int), 0);
    const int eb = (N_EDGES + 255) / 256;
    k_deg<<<eb, 256>>>(ei);
    k_scan<<<1, 1024>>>();
    k_fill<<<eb, 256>>>(ei);

    k_bninit<<<1, DD>>>();

    float4* bufs[4] = { (float4*)p_xa, (float4*)p_xb, (float4*)p_xa, (float4*)p_xb };
    for (int l = 0; l < NLAYERS; l++) {
        cudaMemsetAsync(p_stats, 0, 2 * DD * sizeof(float), 0);
        k_mlp<<<148, 256, mlp_smem>>>(bufs[l], bufs[l+1],
                                      W1 + l*DD*DD, b1 + l*DD,
                                      W2 + l*DD*DD, b2 + l*DD, eps + l);
        k_bnparam<<<1, DD>>>(gamma + l*DD, beta + l*DD);
    }

    cudaMemsetAsync(p_pool, 0, (size_t)N_GRAPHS * DD * sizeof(float), 0);
    cudaMemsetAsync(p_cnt, 0, N_GRAPHS * sizeof(float), 0);
    const int pool_blocks = (N_NODES * 32 + 255) / 256;
    k_pool<<<pool_blocks, 256>>>(batch, bufs[NLAYERS]);
    k_final<<<N_GRAPHS, DD>>>(We, be, out);
}

// round 5
// speedup vs baseline: 1.5151x; 1.2049x over previous
#include <cuda_runtime.h>

#define N_NODES 50000
#define N_EDGES 800000
#define N_GRAPHS 256
#define DD 128
#define DV 32                   // float4 per node row
#define NLAYERS 3
#define TILE 64
#define NTILES ((N_NODES + TILE - 1) / TILE)
#define BN_EPS 1e-5f

// -------- scratch (16B-aligned via float4) --------
__device__ float4 g_xa[N_NODES * DV];
__device__ float4 g_xb[N_NODES * DV];
__device__ int    g_deg[N_NODES];
__device__ int    g_off[N_NODES + 1];
__device__ int    g_cur[N_NODES];
__device__ int    g_csr[N_EDGES];
__device__ float  g_stats[2 * DD];
__device__ float  g_sc[DD];
__device__ float  g_sh[DD];
__device__ float4 g_pool[N_GRAPHS * DV];
__device__ float  g_cnt[N_GRAPHS];

// -------- CSR build --------
__global__ void k_deg(const int* __restrict__ ei) {
    int e = blockIdx.x * blockDim.x + threadIdx.x;
    if (e >= N_EDGES) return;
    unsigned d = (unsigned)ei[N_EDGES + e];
    if (d < N_NODES) atomicAdd(&g_deg[d], 1);
}

__global__ void k_scan() {   // single block, 1024 threads: exclusive scan of g_deg
    __shared__ int sbuf[1024];
    __shared__ int carry;
    if (threadIdx.x == 0) carry = 0;
    __syncthreads();
    for (int base = 0; base < N_NODES; base += 1024) {
        int i = base + threadIdx.x;
        int v = (i < N_NODES) ? g_deg[i] : 0;
        sbuf[threadIdx.x] = v;
        __syncthreads();
        for (int ofs = 1; ofs < 1024; ofs <<= 1) {
            int tv = (threadIdx.x >= ofs) ? sbuf[threadIdx.x - ofs] : 0;
            __syncthreads();
            sbuf[threadIdx.x] += tv;
            __syncthreads();
        }
        if (i < N_NODES) g_off[i + 1] = carry + sbuf[threadIdx.x];
        __syncthreads();
        if (threadIdx.x == 0) carry += sbuf[1023];
        __syncthreads();
    }
    if (threadIdx.x == 0) g_off[0] = 0;
}

__global__ void k_fill(const int* __restrict__ ei) {
    int e = blockIdx.x * blockDim.x + threadIdx.x;
    if (e >= N_EDGES) return;
    unsigned s = (unsigned)ei[e];
    unsigned d = (unsigned)ei[N_EDGES + e];
    if (s >= N_NODES || d >= N_NODES) return;
    int pos = atomicAdd(&g_cur[d], 1);
    g_csr[g_off[d] + pos] = (int)s;
}

// -------- BN fold params --------
__global__ void k_bninit() {
    int t = threadIdx.x;
    g_sc[t] = 1.0f;
    g_sh[t] = 0.0f;
}
__global__ void k_bnparam(const float* __restrict__ gamma, const float* __restrict__ beta) {
    int t = threadIdx.x;
    const float invN = 1.0f / (float)N_NODES;
    float s = g_stats[t], q = g_stats[DD + t];
    float mu = s * invN;
    float var = fmaf(q, invN, -mu * mu);
    float sc = gamma[t] * rsqrtf(var + BN_EPS);
    g_sc[t] = sc;
    g_sh[t] = beta[t] - mu * sc;
}

// -------- fused layer: CSR gather + BN-fold + MLP + stats --------
// Warp-private tile rows: warp w owns rows [4w, 4w+4) of shb/stb, so only
// __syncwarp() is needed between phases -> warps pipeline independently.
extern __shared__ float smem[];
__global__ void __launch_bounds__(512, 1) k_mlp(
    const float4* __restrict__ in, float4* __restrict__ out,
    const float* __restrict__ W1, const float* __restrict__ b1,
    const float* __restrict__ W2, const float* __restrict__ b2,
    const float* __restrict__ epsp)
{
    float* sW1 = smem;                    // 128*128
    float* sW2 = sW1 + DD * DD;           // 128*128
    float* sb1 = sW2 + DD * DD;           // 128
    float* sb2 = sb1 + DD;                // 128
    float* ssc = sb2 + DD;                // 128
    float* ssh = ssc + DD;                // 128
    float* shb = ssh + DD;                // TILE*128
    float* stb = shb + TILE * DD;         // TILE*128
    float* sst = stb + TILE * DD;         // 2*128

    const int t = threadIdx.x;
    const int lane = t & 31, warp = t >> 5;

    for (int i = t; i < DD * DD / 4; i += 512) {
        reinterpret_cast<float4*>(sW1)[i] = reinterpret_cast<const float4*>(W1)[i];
        reinterpret_cast<float4*>(sW2)[i] = reinterpret_cast<const float4*>(W2)[i];
    }
    if (t < DD) { sb1[t] = b1[t]; sb2[t] = b2[t]; ssc[t] = g_sc[t]; ssh[t] = g_sh[t]; }
    const float eps1 = 1.0f + epsp[0];
    __syncthreads();

    const float4 sc4 = reinterpret_cast<const float4*>(ssc)[lane];
    const float4 sh4 = reinterpret_cast<const float4*>(ssh)[lane];
    const float b1x = sb1[lane*4], b1y = sb1[lane*4+1], b1z = sb1[lane*4+2], b1w = sb1[lane*4+3];
    const float b2x = sb2[lane*4], b2y = sb2[lane*4+1], b2z = sb2[lane*4+2], b2w = sb2[lane*4+3];

    float sv[4] = {0.f, 0.f, 0.f, 0.f};
    float qv[4] = {0.f, 0.f, 0.f, 0.f};

    for (int tile = blockIdx.x; tile < NTILES; tile += gridDim.x) {
        const int nb = tile * TILE;

        // ---- gather (CSR) + BN-fold + GIN combine -> h rows (warp-private) ----
        #pragma unroll
        for (int r = 0; r < 4; r++) {
            int node = nb + warp * 4 + r;
            float4 acc = make_float4(0.f, 0.f, 0.f, 0.f);
            float4 xv  = make_float4(0.f, 0.f, 0.f, 0.f);
            float fdeg = 0.f;
            if (node < N_NODES) {
                int beg = g_off[node], end = g_off[node + 1];
                fdeg = (float)(end - beg);
                xv = in[node * DV + lane];
                int e = beg;
                for (; e + 4 <= end; e += 4) {
                    int j0 = g_csr[e], j1 = g_csr[e+1], j2 = g_csr[e+2], j3 = g_csr[e+3];
                    float4 v0 = in[j0 * DV + lane];
                    float4 v1 = in[j1 * DV + lane];
                    float4 v2 = in[j2 * DV + lane];
                    float4 v3 = in[j3 * DV + lane];
                    acc.x += (v0.x + v1.x) + (v2.x + v3.x);
                    acc.y += (v0.y + v1.y) + (v2.y + v3.y);
                    acc.z += (v0.z + v1.z) + (v2.z + v3.z);
                    acc.w += (v0.w + v1.w) + (v2.w + v3.w);
                }
                for (; e < end; e++) {
                    int j0 = g_csr[e];
                    float4 v0 = in[j0 * DV + lane];
                    acc.x += v0.x; acc.y += v0.y; acc.z += v0.z; acc.w += v0.w;
                }
            }
            float f = eps1 + fdeg;
            float4 h;
            h.x = fmaf(sc4.x, fmaf(eps1, xv.x, acc.x), f * sh4.x);
            h.y = fmaf(sc4.y, fmaf(eps1, xv.y, acc.y), f * sh4.y);
            h.z = fmaf(sc4.z, fmaf(eps1, xv.z, acc.z), f * sh4.z);
            h.w = fmaf(sc4.w, fmaf(eps1, xv.w, acc.w), f * sh4.w);
            reinterpret_cast<float4*>(shb)[(warp * 4 + r) * DV + lane] = h;
        }
        __syncwarp();

        // ---- GEMM1: t = relu(h @ W1 + b1), 4 nodes x 4 outs per thread ----
        {
            float a[4][4];
            #pragma unroll
            for (int r = 0; r < 4; r++) { a[r][0]=b1x; a[r][1]=b1y; a[r][2]=b1z; a[r][3]=b1w; }
            #pragma unroll 8
            for (int d0 = 0; d0 < DD; d0 += 4) {
                float4 hv[4];
                #pragma unroll
                for (int r = 0; r < 4; r++)
                    hv[r] = reinterpret_cast<const float4*>(shb)[(warp*4 + r)*DV + (d0 >> 2)];
                #pragma unroll
                for (int dd = 0; dd < 4; dd++) {
                    float4 w = reinterpret_cast<const float4*>(sW1)[(d0 + dd)*DV + lane];
                    #pragma unroll
                    for (int r = 0; r < 4; r++) {
                        float hr = (dd == 0) ? hv[r].x : (dd == 1) ? hv[r].y : (dd == 2) ? hv[r].z : hv[r].w;
                        a[r][0] = fmaf(hr, w.x, a[r][0]);
                        a[r][1] = fmaf(hr, w.y, a[r][1]);
                        a[r][2] = fmaf(hr, w.z, a[r][2]);
                        a[r][3] = fmaf(hr, w.w, a[r][3]);
                    }
                }
            }
            #pragma unroll
            for (int r = 0; r < 4; r++) {
                float4 tv = make_float4(fmaxf(a[r][0],0.f), fmaxf(a[r][1],0.f),
                                        fmaxf(a[r][2],0.f), fmaxf(a[r][3],0.f));
                reinterpret_cast<float4*>(stb)[(warp*4 + r)*DV + lane] = tv;
            }
        }
        __syncwarp();

        // ---- GEMM2: y = relu(t @ W2 + b2); write out; BN stats ----
        {
            float c[4][4];
            #pragma unroll
            for (int r = 0; r < 4; r++) { c[r][0]=b2x; c[r][1]=b2y; c[r][2]=b2z; c[r][3]=b2w; }
            #pragma unroll 8
            for (int d0 = 0; d0 < DD; d0 += 4) {
                float4 uv[4];
                #pragma unroll
                for (int r = 0; r < 4; r++)
                    uv[r] = reinterpret_cast<const float4*>(stb)[(warp*4 + r)*DV + (d0 >> 2)];
                #pragma unroll
                for (int dd = 0; dd < 4; dd++) {
                    float4 w = reinterpret_cast<const float4*>(sW2)[(d0 + dd)*DV + lane];
                    #pragma unroll
                    for (int r = 0; r < 4; r++) {
                        float ur = (dd == 0) ? uv[r].x : (dd == 1) ? uv[r].y : (dd == 2) ? uv[r].z : uv[r].w;
                        c[r][0] = fmaf(ur, w.x, c[r][0]);
                        c[r][1] = fmaf(ur, w.y, c[r][1]);
                        c[r][2] = fmaf(ur, w.z, c[r][2]);
                        c[r][3] = fmaf(ur, w.w, c[r][3]);
                    }
                }
            }
            #pragma unroll
            for (int r = 0; r < 4; r++) {
                int node = nb + warp * 4 + r;
                if (node < N_NODES) {
                    float4 y = make_float4(fmaxf(c[r][0],0.f), fmaxf(c[r][1],0.f),
                                           fmaxf(c[r][2],0.f), fmaxf(c[r][3],0.f));
                    out[node * DV + lane] = y;
                    sv[0] += y.x; sv[1] += y.y; sv[2] += y.z; sv[3] += y.w;
                    qv[0] += y.x*y.x; qv[1] += y.y*y.y; qv[2] += y.z*y.z; qv[3] += y.w*y.w;
                }
            }
        }
        __syncwarp();
    }

    // ---- block stat reduction -> global ----
    __syncthreads();
    if (t < 2 * DD) sst[t] = 0.f;
    __syncthreads();
    const int og = lane * 4;
    atomicAdd(&sst[og],      sv[0]); atomicAdd(&sst[og+1],    sv[1]);
    atomicAdd(&sst[og+2],    sv[2]); atomicAdd(&sst[og+3],    sv[3]);
    atomicAdd(&sst[DD+og],   qv[0]); atomicAdd(&sst[DD+og+1], qv[1]);
    atomicAdd(&sst[DD+og+2], qv[2]); atomicAdd(&sst[DD+og+3], qv[3]);
    __syncthreads();
    if (t < DD) {
        atomicAdd(&g_stats[t],      sst[t]);
        atomicAdd(&g_stats[DD + t], sst[DD + t]);
    }
}

// -------- global mean pool on raw y3 --------
__global__ void k_pool(const int* __restrict__ batch, const float4* __restrict__ in) {
    int idx = blockIdx.x * blockDim.x + threadIdx.x;
    int n = idx >> 5;
    int k = idx & 31;
    if (n >= N_NODES) return;
    unsigned g = (unsigned)batch[n];
    if (g >= N_GRAPHS) return;
    float4 v = in[n * DV + k];
    atomicAdd(&g_pool[g * DV + k], v);
    if (k == 0) atomicAdd(&g_cnt[g], 1.0f);
}

// -------- head: out = (BN-fold(pool/cnt)) @ We + be --------
__global__ void k_final(const float* __restrict__ We, const float* __restrict__ be,
                        float* __restrict__ out) {
    __shared__ float sp[DD];
    int b = blockIdx.x;
    int o = threadIdx.x;
    float c = fmaxf(g_cnt[b], 1.0f);
    float sum = reinterpret_cast<const float*>(g_pool)[b * DD + o];
    sp[o] = fmaf(g_sc[o], sum / c, g_sh[o]);
    __syncthreads();
    float acc = be[o];
    #pragma unroll 4
    for (int d = 0; d < DD; d++) acc = fmaf(sp[d], We[d * DD + o], acc);
    out[b * DD + o] = acc;
}

extern "C" void kernel_launch(void* const* d_in, const int* in_sizes, int n_in,
                              void* d_out, int out_size) {
    const float* x     = (const float*)d_in[0];
    const int*   ei    = (const int*)d_in[1];
    const int*   batch = (const int*)d_in[2];
    const float* W1    = (const float*)d_in[3];
    const float* b1    = (const float*)d_in[4];
    const float* W2    = (const float*)d_in[5];
    const float* b2    = (const float*)d_in[6];
    const float* eps   = (const float*)d_in[7];
    const float* gamma = (const float*)d_in[8];
    const float* beta  = (const float*)d_in[9];
    const float* We    = (const float*)d_in[10];
    const float* be    = (const float*)d_in[11];
    float* out = (float*)d_out;

    void *p_xa, *p_xb, *p_deg, *p_cur, *p_stats, *p_pool, *p_cnt;
    cudaGetSymbolAddress(&p_xa, g_xa);
    cudaGetSymbolAddress(&p_xb, g_xb);
    cudaGetSymbolAddress(&p_deg, g_deg);
    cudaGetSymbolAddress(&p_cur, g_cur);
    cudaGetSymbolAddress(&p_stats, g_stats);
    cudaGetSymbolAddress(&p_pool, g_pool);
    cudaGetSymbolAddress(&p_cnt, g_cnt);

    const int mlp_smem = (2*DD*DD + 4*DD + 2*TILE*DD + 2*DD) * (int)sizeof(float);
    cudaFuncSetAttribute(k_mlp, cudaFuncAttributeMaxDynamicSharedMemorySize, mlp_smem);

    // load features
    cudaMemcpyAsync(p_xa, x, (size_t)N_NODES * DD * sizeof(float),
                    cudaMemcpyDeviceToDevice, 0);

    // CSR build (once; reused across layers)
    cudaMemsetAsync(p_deg, 0, N_NODES * sizeof(int), 0);
    cudaMemsetAsync(p_cur, 0, N_NODES * sizeof(int), 0);
    const int eb = (N_EDGES + 255) / 256;
    k_deg<<<eb, 256>>>(ei);
    k_scan<<<1, 1024>>>();
    k_fill<<<eb, 256>>>(ei);

    k_bninit<<<1, DD>>>();

    float4* bufs[4] = { (float4*)p_xa, (float4*)p_xb, (float4*)p_xa, (float4*)p_xb };
    for (int l = 0; l < NLAYERS; l++) {
        cudaMemsetAsync(p_stats, 0, 2 * DD * sizeof(float), 0);
        k_mlp<<<148, 512, mlp_smem>>>(bufs[l], bufs[l+1],
                                      W1 + l*DD*DD, b1 + l*DD,
                                      W2 + l*DD*DD, b2 + l*DD, eps + l);
        k_bnparam<<<1, DD>>>(gamma + l*DD, beta + l*DD);
    }

    cudaMemsetAsync(p_pool, 0, (size_t)N_GRAPHS * DD * sizeof(float), 0);
    cudaMemsetAsync(p_cnt, 0, N_GRAPHS * sizeof(float), 0);
    const int pool_blocks = (N_NODES * 32 + 255) / 256;
    k_pool<<<pool_blocks, 256>>>(batch, bufs[NLAYERS]);
    k_final<<<N_GRAPHS, DD>>>(We, be, out);
}